// round 5
// baseline (speedup 1.0000x reference)
#include <cuda_runtime.h>
#include <cstdint>

// Problem constants: N=4096 nodes, T=128 timesteps, D=64, E=131072 edges.
#define NN 4096
#define TT 128
#define DD 64
#define CAP 128      // per-dst bucket capacity (4 sub-buckets x 32)
#define NSUB 4
#define SUBCAP 32    // in-degree/sub ~ Poisson(8); P(>32) ~ 1e-11

// ---------------- scratch (device globals; zero-init at load; self-cleaning) ----------------
__device__ float g_rs[NN];             // row-sum EXCESS over 1 -> zero-init valid; reset in k_bucket
__device__ int   g_scnt[NN * NSUB];    // sub-counters; reset by k_dedup after reading
__device__ int   g_bkey[NN * CAP];     // bucket: packed (src<<18)|e
__device__ float g_bw[NN * CAP];       // bucket: weights
__device__ int   g_ccnt[NN];           // compacted winner count (overwritten each launch)
__device__ int   g_csr_src[NN * CAP];  // compacted winner srcs
__device__ float g_csr_w[NN * CAP];    // compacted winner weights

__device__ __forceinline__ float tanh_fast(float x) {
    float y;
    asm("tanh.approx.f32 %0, %1;" : "=f"(y) : "f"(x));
    return y;
}

// ---------------- kernel 1: scatter edges into sub-buckets (4 edges/thread) ----------------
__device__ __forceinline__ void bucket_one(int e, int src, int dst, float w) {
    int sub = e & (NSUB - 1);
    int p = atomicAdd(&g_scnt[dst * NSUB + sub], 1);
    if (p < SUBCAP) {
        int slot = dst * CAP + sub * SUBCAP + p;
        g_bkey[slot] = (src << 18) | e;    // src:12b key | e:17b tiebreak
        g_bw[slot] = w;
    }
}

__global__ void k_bucket(const int* __restrict__ ei,
                         const float* __restrict__ ew, int E) {
    int tid = blockIdx.x * blockDim.x + threadIdx.x;
    if (tid < NN) g_rs[tid] = 0.0f;         // reset before k_dedup accumulates
    int e0 = tid * 4;
    if (e0 + 3 < E) {
        int4   s4 = *reinterpret_cast<const int4*>(ei + e0);
        int4   d4 = *reinterpret_cast<const int4*>(ei + E + e0);
        float4 w4 = *reinterpret_cast<const float4*>(ew + e0);
        bucket_one(e0 + 0, s4.x, d4.x, w4.x);
        bucket_one(e0 + 1, s4.y, d4.y, w4.y);
        bucket_one(e0 + 2, s4.z, d4.z, w4.z);
        bucket_one(e0 + 3, s4.w, d4.w, w4.w);
    } else {
        for (int e = e0; e < E; e++)
            bucket_one(e, ei[e], ei[E + e], ew[e]);
    }
}

// ---------------- kernel 2: per-bucket last-write-wins dedup -> compacted CSR + row sums ----------------
__global__ void __launch_bounds__(CAP) k_dedup() {
    __shared__ int   skey[CAP];
    __shared__ float swt[CAP];
    __shared__ int   s_cnt[NSUB];
    __shared__ int   warp_tot[NSUB];
    __shared__ int   warp_base[NSUB];

    int i = blockIdx.x;
    int t = threadIdx.x;
    int sub = t >> 5, lane = t & 31;

    if (t < NSUB) s_cnt[t] = min(g_scnt[i * NSUB + t], SUBCAP);
    __syncthreads();

    bool valid = lane < s_cnt[sub];
    int   key = valid ? g_bkey[i * CAP + t] : -1;
    float w   = valid ? g_bw[i * CAP + t]   : 0.0f;
    skey[t] = key;
    swt[t]  = w;
    __syncthreads();

    bool winner = valid;
    if (valid) {
        #pragma unroll 8
        for (int k = 0; k < CAP; k++) {
            int kk = skey[k];
            if (kk >= 0 && ((kk ^ key) >> 18) == 0 && kk > key) winner = false;
        }
    }
    if (winner) atomicAdd(&g_rs[key >> 18], w);   // no return -> RED

    unsigned m = __ballot_sync(0xffffffff, winner);
    if (lane == 0) warp_tot[sub] = __popc(m);
    __syncthreads();
    if (t == 0) {
        int b = 0;
        #pragma unroll
        for (int k = 0; k < NSUB; k++) { warp_base[k] = b; b += warp_tot[k]; }
        g_ccnt[i] = b;
    }
    __syncthreads();
    if (winner) {
        int pos = warp_base[sub] + __popc(m & ((1u << lane) - 1));
        g_csr_src[i * CAP + pos] = key >> 18;
        g_csr_w[i * CAP + pos]   = w;
    }
    if (t < NSUB) g_scnt[i * NSUB + t] = 0;       // self-clean for next replay
}

// ---------------- kernel 3: SpMM + tanh epilogue, one block per dst row ----------------
// d[i] = rsqrt(1 + rs[i]);  ax[i,t] = d[i]*( d[i]*x[i,t] + sum w * d[s] * x[s,t] )
// out[i,t,d] = tanh(ax[i,t] * wv[d])
__global__ void __launch_bounds__(128) k_fused(const float* __restrict__ x,
                                               const float* __restrict__ wv,
                                               float4* __restrict__ out) {
    __shared__ int    ss[CAP];
    __shared__ float  sw[CAP];
    __shared__ float  s_ax[TT];
    __shared__ float4 s_w[DD / 4];

    int i = blockIdx.x;
    int t = threadIdx.x;
    if (t < DD / 4) s_w[t] = reinterpret_cast<const float4*>(wv)[t];

    int cnt = g_ccnt[i];
    float dinv_i = rsqrtf(1.0f + g_rs[i]);
    float acc = dinv_i * x[i * TT + t];     // self-loop term (outer d[i] applied at end)
    if (t < cnt) {
        int s = g_csr_src[i * CAP + t];
        ss[t] = s;
        sw[t] = g_csr_w[i * CAP + t] * rsqrtf(1.0f + g_rs[s]);
    }
    __syncthreads();

    #pragma unroll 4
    for (int j = 0; j < cnt; j++)
        acc = fmaf(sw[j], x[ss[j] * TT + t], acc);

    s_ax[t] = dinv_i * acc;
    __syncthreads();

    // 128*64 floats = 2048 float4 per row, coalesced streaming stores (evict-first)
    float4* outb = out + (size_t)i * (TT * DD / 4);
    #pragma unroll
    for (int k = t; k < TT * DD / 4; k += 128) {
        float  a  = s_ax[k >> 4];
        float4 w4 = s_w[k & 15];
        float4 r;
        r.x = tanh_fast(a * w4.x);
        r.y = tanh_fast(a * w4.y);
        r.z = tanh_fast(a * w4.z);
        r.w = tanh_fast(a * w4.w);
        __stcs(outb + k, r);
    }
}

extern "C" void kernel_launch(void* const* d_in, const int* in_sizes, int n_in,
                              void* d_out, int out_size) {
    const float* x  = (const float*)d_in[0];   // [4096,128] fp32
    const int*   ei = (const int*)d_in[1];     // [2,E] int32 (JAX x64 disabled)
    const float* ew = (const float*)d_in[2];   // [E] fp32
    const float* wv = (const float*)d_in[3];   // [1,64] fp32

    int E = in_sizes[2];
    int nthreads = (E + 3) / 4;

    k_bucket<<<(nthreads + 255) / 256, 256>>>(ei, ew, E);
    k_dedup<<<NN, CAP>>>();
    k_fused<<<NN, 128>>>(x, wv, (float4*)d_out);
    (void)n_in; (void)out_size;
}

// round 6
// speedup vs baseline: 1.3681x; 1.3681x over previous
#include <cuda_runtime.h>
#include <cstdint>

// Problem constants: N=4096 nodes, T=128 timesteps, D=64, E=131072 edges.
#define NN 4096
#define TT 128
#define DD 64
#define NSUB 8
#define SUBCAP 32    // per-(dst,sub) count ~ Poisson(4); P(>32) ~ 1e-18
#define CAP (NSUB * SUBCAP)   // 256 slots per dst

// ---------------- scratch (device globals; zero-init at load; self-cleaning) ----------------
__device__ float g_rs[NN];             // row-sum EXCESS over 1; reset in k_bucket, accumulated in k_dedup
__device__ int   g_scnt[NN * NSUB];    // sub-counters; reset by k_dedup after reading
__device__ int   g_bkey[NN * CAP];     // bucket: packed (src<<18)|e
__device__ float g_bw[NN * CAP];       // bucket: weights
__device__ int   g_ccnt[NN];           // compacted winner count (overwritten each launch)
__device__ int   g_csr_src[NN * CAP];  // compacted winner srcs
__device__ float g_csr_w[NN * CAP];    // compacted winner weights

__device__ __forceinline__ float tanh_fast(float x) {
    float y;
    asm("tanh.approx.f32 %0, %1;" : "=f"(y) : "f"(x));
    return y;
}

// ---------------- kernel 1: scatter edges into 8-way sharded dst buckets (1 edge/thread) ----------------
__global__ void k_bucket(const int* __restrict__ ei,
                         const float* __restrict__ ew, int E) {
    int e = blockIdx.x * blockDim.x + threadIdx.x;
    if (e < NN) g_rs[e] = 0.0f;             // reset before k_dedup accumulates
    if (e >= E) return;
    int src = ei[e];
    int dst = ei[E + e];
    int sub = e & (NSUB - 1);
    int p = atomicAdd(&g_scnt[dst * NSUB + sub], 1);
    if (p < SUBCAP) {
        int slot = dst * CAP + sub * SUBCAP + p;
        g_bkey[slot] = (src << 18) | e;     // src:12b key | e:17b tiebreak
        g_bw[slot]   = ew[e];
    }
}

// ---------------- kernel 2: compact ragged sub-buckets, last-write-wins dedup, row sums ----------------
__global__ void __launch_bounds__(CAP) k_dedup() {
    __shared__ int   skey[CAP];
    __shared__ float swt[CAP];
    __shared__ int   warp_cnt[NSUB];
    __shared__ int   warp_base[NSUB];
    __shared__ int   s_total;
    __shared__ int   s_pos;

    int i = blockIdx.x;
    int t = threadIdx.x;
    int sub = t >> 5, lane = t & 31;

    int cw = 0;
    if (lane == 0) cw = min(g_scnt[i * NSUB + sub], SUBCAP);
    cw = __shfl_sync(0xffffffff, cw, 0);
    if (lane == 0) warp_cnt[sub] = cw;
    if (t == 0) s_pos = 0;
    __syncthreads();
    if (t == 0) {
        int b = 0;
        #pragma unroll
        for (int k = 0; k < NSUB; k++) { warp_base[k] = b; b += warp_cnt[k]; }
        s_total = b;
    }
    __syncthreads();

    // dense compaction (valid lanes are contiguous per sub-bucket)
    int   key = -1;
    float w   = 0.0f;
    if (lane < cw) {
        key = g_bkey[i * CAP + sub * SUBCAP + lane];
        w   = g_bw[i * CAP + sub * SUBCAP + lane];
        int dpos = warp_base[sub] + lane;
        skey[dpos] = key;
        swt[dpos]  = w;
    }
    if (t < NSUB) g_scnt[i * NSUB + t] = 0;   // self-clean for next replay
    __syncthreads();

    int cnt = s_total;                        // typically ~32
    if (t < cnt) {
        int   kj = skey[t];
        float wj = swt[t];
        bool winner = true;
        for (int k = 0; k < cnt; k++) {
            int kk = skey[k];
            if (((kk ^ kj) >> 18) == 0 && kk > kj) winner = false;  // same src, newer edge
        }
        if (winner) {
            atomicAdd(&g_rs[kj >> 18], wj);   // no-return -> RED, spread addresses
            int pos = atomicAdd(&s_pos, 1);   // order irrelevant to the gather
            g_csr_src[i * CAP + pos] = kj >> 18;
            g_csr_w[i * CAP + pos]   = wj;
        }
    }
    __syncthreads();
    if (t == 0) g_ccnt[i] = s_pos;
}

// ---------------- kernel 3: SpMM + tanh epilogue, one block per dst row ----------------
// d[i] = rsqrt(1 + rs[i]);  ax[i,t] = d[i]*( d[i]*x[i,t] + sum w * d[s] * x[s,t] )
// out[i,t,d] = tanh(ax[i,t] * wv[d])
__global__ void __launch_bounds__(128) k_fused(const float* __restrict__ x,
                                               const float* __restrict__ wv,
                                               float4* __restrict__ out) {
    __shared__ int    ss[CAP];
    __shared__ float  sw[CAP];
    __shared__ float  s_ax[TT];
    __shared__ float4 s_w[DD / 4];

    int i = blockIdx.x;
    int t = threadIdx.x;
    if (t < DD / 4) s_w[t] = reinterpret_cast<const float4*>(wv)[t];

    int cnt = g_ccnt[i];
    float dinv_i = rsqrtf(1.0f + g_rs[i]);
    float acc = dinv_i * x[i * TT + t];     // self-loop term (outer d[i] applied at end)
    for (int base = 0; base < cnt; base += 128) {
        if (base + t < cnt) {
            int s = g_csr_src[i * CAP + base + t];
            ss[t] = s;
            sw[t] = g_csr_w[i * CAP + base + t] * rsqrtf(1.0f + g_rs[s]);
        }
        __syncthreads();
        int n = min(128, cnt - base);
        #pragma unroll 4
        for (int j = 0; j < n; j++)
            acc = fmaf(sw[j], x[ss[j] * TT + t], acc);
        __syncthreads();
    }

    s_ax[t] = dinv_i * acc;
    __syncthreads();

    // 128*64 floats = 2048 float4 per row, coalesced streaming stores (evict-first)
    float4* outb = out + (size_t)i * (TT * DD / 4);
    #pragma unroll
    for (int k = t; k < TT * DD / 4; k += 128) {
        float  a  = s_ax[k >> 4];
        float4 w4 = s_w[k & 15];
        float4 r;
        r.x = tanh_fast(a * w4.x);
        r.y = tanh_fast(a * w4.y);
        r.z = tanh_fast(a * w4.z);
        r.w = tanh_fast(a * w4.w);
        __stcs(outb + k, r);
    }
}

extern "C" void kernel_launch(void* const* d_in, const int* in_sizes, int n_in,
                              void* d_out, int out_size) {
    const float* x  = (const float*)d_in[0];   // [4096,128] fp32
    const int*   ei = (const int*)d_in[1];     // [2,E] int32 (JAX x64 disabled)
    const float* ew = (const float*)d_in[2];   // [E] fp32
    const float* wv = (const float*)d_in[3];   // [1,64] fp32

    int E = in_sizes[2];

    k_bucket<<<(E + 255) / 256, 256>>>(ei, ew, E);
    k_dedup<<<NN, CAP>>>();
    k_fused<<<NN, 128>>>(x, wv, (float4*)d_out);
    (void)n_in; (void)out_size;
}

// round 7
// speedup vs baseline: 1.4724x; 1.0762x over previous
#include <cuda_runtime.h>
#include <cstdint>

// Problem constants: N=4096 nodes, T=128 timesteps, D=64, E=131072 edges.
#define NN 4096
#define TT 128
#define DD 64
#define NSUB 8
#define SUBCAP 32                 // per-(dst,sub) ~ Poisson(4); P(>32) ~ 1e-18
#define CAP (NSUB * SUBCAP)       // 256 slots per dst
#define ROWS_PER_BLK 8            // k_dedup: one warp per dst row

typedef unsigned long long u64;

// ---------------- scratch (device globals; zero-init at load; self-cleaning) ----------------
__device__ float g_rs[NN];           // row-sum EXCESS over 1; reset in k_bucket, accumulated in k_dedup
__device__ int   g_scnt[NN * NSUB];  // sub-counters; reset by k_dedup after reading
__device__ u64   g_bkt[NN * CAP];    // packed bucket: (((src<<18)|e) << 32) | w_bits
__device__ int   g_ccnt[NN];         // compacted winner count (overwritten each launch)
__device__ u64   g_csr[NN * CAP];    // packed CSR: (src << 32) | w_bits

__device__ __forceinline__ float tanh_fast(float x) {
    float y;
    asm("tanh.approx.f32 %0, %1;" : "=f"(y) : "f"(x));
    return y;
}

// ---------------- kernel 1: scatter edges into 8-way sharded dst buckets, one STG.64 each ----------------
__global__ void k_bucket(const int* __restrict__ ei,
                         const float* __restrict__ ew, int E) {
    int e = blockIdx.x * blockDim.x + threadIdx.x;
    if (e < NN) g_rs[e] = 0.0f;             // reset before k_dedup accumulates (untouched here otherwise)
    if (e >= E) return;
    int src = ei[e];
    int dst = ei[E + e];
    int sub = e & (NSUB - 1);
    int p = atomicAdd(&g_scnt[dst * NSUB + sub], 1);
    if (p < SUBCAP) {
        u64 v = ((u64)(unsigned)((src << 18) | e) << 32) | (u64)__float_as_uint(ew[e]);
        g_bkt[dst * CAP + sub * SUBCAP + p] = v;
    }
}

// ---------------- kernel 2: one warp per dst row: compact, last-write-wins dedup, row sums, CSR ----------------
__global__ void __launch_bounds__(ROWS_PER_BLK * 32) k_dedup() {
    __shared__ u64 sm[ROWS_PER_BLK][CAP];
    __shared__ int s_pos[ROWS_PER_BLK];

    int w    = threadIdx.x >> 5;
    int lane = threadIdx.x & 31;
    int i    = blockIdx.x * ROWS_PER_BLK + w;

    // sub-bucket counts: lane s holds count of sub s; broadcast via shuffle
    int cval = 0;
    if (lane < NSUB) {
        cval = min(g_scnt[i * NSUB + lane], SUBCAP);
        g_scnt[i * NSUB + lane] = 0;                 // self-clean for next replay
    }
    int c[NSUB], base[NSUB];
    int tot = 0;
    #pragma unroll
    for (int s = 0; s < NSUB; s++) {
        c[s] = __shfl_sync(0xffffffff, cval, s);
        base[s] = tot;
        tot += c[s];
    }
    if (lane == 0) s_pos[w] = 0;

    // dense compaction of ragged sub-buckets into smem
    #pragma unroll
    for (int slot = 0; slot < CAP; slot += 32) {
        int s = (slot + lane) >> 5;                  // sub index of this slot
        int l = (slot + lane) & 31;
        if (l < c[s]) sm[w][base[s] + l] = g_bkt[i * CAP + slot + lane];
    }
    __syncwarp();

    // dedup scan: same src (key>>18), larger packed key (newer edge) wins
    for (int j = lane; j < tot; j += 32) {
        u64 vj = sm[w][j];
        int kj = (int)(vj >> 32);
        bool winner = true;
        for (int k = 0; k < tot; k++) {
            int kk = (int)(sm[w][k] >> 32);
            if (((kk ^ kj) >> 18) == 0 && kk > kj) winner = false;
        }
        if (winner) {
            int src = kj >> 18;
            float wt = __uint_as_float((unsigned)vj);
            atomicAdd(&g_rs[src], wt);               // no-return -> RED, spread addresses
            int pos = atomicAdd(&s_pos[w], 1);       // order irrelevant to the gather
            g_csr[i * CAP + pos] = ((u64)(unsigned)src << 32) | (u64)__float_as_uint(wt);
        }
    }
    __syncwarp();
    if (lane == 0) g_ccnt[i] = s_pos[w];
}

// ---------------- kernel 3: SpMM + tanh epilogue, one block per dst row ----------------
// d[i] = rsqrt(1 + rs[i]);  ax[i,t] = d[i]*( d[i]*x[i,t] + sum w * d[s] * x[s,t] )
// out[i,t,d] = tanh(ax[i,t] * wv[d])
__global__ void __launch_bounds__(128) k_fused(const float* __restrict__ x,
                                               const float* __restrict__ wv,
                                               float4* __restrict__ out) {
    __shared__ int    ss[128];
    __shared__ float  sw[128];
    __shared__ float  s_ax[TT];
    __shared__ float4 s_w[DD / 4];

    int i = blockIdx.x;
    int t = threadIdx.x;
    if (t < DD / 4) s_w[t] = reinterpret_cast<const float4*>(wv)[t];

    int cnt = g_ccnt[i];
    float dinv_i = rsqrtf(1.0f + g_rs[i]);
    float acc = dinv_i * x[i * TT + t];     // self-loop term (outer d[i] applied at end)

    for (int bse = 0; bse < cnt; bse += 128) {
        if (bse + t < cnt) {
            u64 v = g_csr[i * CAP + bse + t];
            int s = (int)(v >> 32);
            ss[t] = s;
            sw[t] = __uint_as_float((unsigned)v) * rsqrtf(1.0f + g_rs[s]);
        }
        __syncthreads();
        int n = min(128, cnt - bse);
        #pragma unroll 4
        for (int j = 0; j < n; j++)
            acc = fmaf(sw[j], x[ss[j] * TT + t], acc);
        __syncthreads();
    }

    s_ax[t] = dinv_i * acc;
    __syncthreads();

    // 128*64 floats = 2048 float4 per row, coalesced streaming stores (evict-first)
    float4* outb = out + (size_t)i * (TT * DD / 4);
    #pragma unroll
    for (int k = t; k < TT * DD / 4; k += 128) {
        float  a  = s_ax[k >> 4];
        float4 w4 = s_w[k & 15];
        float4 r;
        r.x = tanh_fast(a * w4.x);
        r.y = tanh_fast(a * w4.y);
        r.z = tanh_fast(a * w4.z);
        r.w = tanh_fast(a * w4.w);
        __stcs(outb + k, r);
    }
}

extern "C" void kernel_launch(void* const* d_in, const int* in_sizes, int n_in,
                              void* d_out, int out_size) {
    const float* x  = (const float*)d_in[0];   // [4096,128] fp32
    const int*   ei = (const int*)d_in[1];     // [2,E] int32 (JAX x64 disabled)
    const float* ew = (const float*)d_in[2];   // [E] fp32
    const float* wv = (const float*)d_in[3];   // [1,64] fp32

    int E = in_sizes[2];

    k_bucket<<<(E + 255) / 256, 256>>>(ei, ew, E);
    k_dedup<<<NN / ROWS_PER_BLK, ROWS_PER_BLK * 32>>>();
    k_fused<<<NN, 128>>>(x, wv, (float4*)d_out);
    (void)n_in; (void)out_size;
}